// round 6
// baseline (speedup 1.0000x reference)
#include <cuda_runtime.h>
#include <cuda_bf16.h>
#include <cstdint>

// Embedding gather: out[r, :] = table[indices[r], :]
// n_rows = B*F = 819200, D = 64 floats (256 B per row).
//
// R5: sm_103a ptxas requires 256-bit (.v8.b32) loads for .L2::evict_last.
// So: 8 lanes per row, 32 B per lane via ld.global.nc.L2::evict_last.v8.b32
// (table biased to stay resident in L2; unique working set ~143 MB vs
// 126 MB L2). Output stores remain .cs evict-first (write-once stream).

static constexpr int D = 64;                // embedding dim (floats)
static constexpr int LANES = 8;             // 32 B per lane
static constexpr int RPT = 4;               // rows per thread
static constexpr int BLOCK = 256;
static constexpr int ROWS_PER_BLOCK = (BLOCK / LANES) * RPT;  // 128

struct V8 { float4 a, b; };

__device__ __forceinline__ V8 ldg_evict_last_32B(const float* p)
{
    V8 v;
    asm volatile("ld.global.nc.L2::evict_last.v8.b32 "
                 "{%0,%1,%2,%3,%4,%5,%6,%7}, [%8];"
                 : "=f"(v.a.x), "=f"(v.a.y), "=f"(v.a.z), "=f"(v.a.w),
                   "=f"(v.b.x), "=f"(v.b.y), "=f"(v.b.z), "=f"(v.b.w)
                 : "l"(p));
    return v;
}

__global__ __launch_bounds__(BLOCK)
void gather_kernel(const int* __restrict__ indices,
                   const float* __restrict__ table,
                   float* __restrict__ out,
                   int n_rows)
{
    const int local_row = threadIdx.x >> 3;   // 0..31
    const int lane      = threadIdx.x & 7;    // 0..7
    const long long row_base = (long long)blockIdx.x * ROWS_PER_BLOCK + local_row;

    int idx[RPT];
    V8  vals[RPT];

    // Phase 1: batched independent index loads
#pragma unroll
    for (int k = 0; k < RPT; k++) {
        const long long r = row_base + (long long)k * (BLOCK / LANES);
        idx[k] = (r < n_rows) ? __ldg(indices + r) : 0;
    }

    // Phase 2: batched independent 32B table gathers, biased to stay in L2
#pragma unroll
    for (int k = 0; k < RPT; k++) {
        const float* src = table + (long long)idx[k] * D + lane * 8;
        vals[k] = ldg_evict_last_32B(src);
    }

    // Phase 3: streaming stores (evict-first; output is write-once)
#pragma unroll
    for (int k = 0; k < RPT; k++) {
        const long long r = row_base + (long long)k * (BLOCK / LANES);
        if (r < n_rows) {
            float4* dst = reinterpret_cast<float4*>(out + r * D) + lane * 2;
            __stcs(dst,     vals[k].a);
            __stcs(dst + 1, vals[k].b);
        }
    }
}

extern "C" void kernel_launch(void* const* d_in, const int* in_sizes, int n_in,
                              void* d_out, int out_size)
{
    const int*   indices = (const int*)d_in[0];
    const float* table   = (const float*)d_in[1];
    float*       out     = (float*)d_out;

    const int n_rows = in_sizes[0];            // B*F = 819200
    const int grid   = (n_rows + ROWS_PER_BLOCK - 1) / ROWS_PER_BLOCK;

    gather_kernel<<<grid, BLOCK>>>(indices, table, out, n_rows);
}

// round 7
// speedup vs baseline: 1.0374x; 1.0374x over previous
#include <cuda_runtime.h>
#include <cuda_bf16.h>
#include <cstdint>

// Embedding gather: out[r, :] = table[indices[r], :]
// n_rows = B*F = 819200, D = 64 floats (256 B per row).
//
// R6: DRAM bytes are at floor (~333 MB measured vs ~353 MB floor); all MLP
// schemes converge at ~57.8us / 73% DRAM = the mixed random-read/stream-write
// HBM ceiling. This round trims the instruction path: pure 32-bit address
// math (all offsets fit u32), no per-row predicates in the main kernel
// (exact tiling; guarded tail kernel handles any remainder).

static constexpr int D      = 64;           // embedding dim (floats)
static constexpr int LANES  = 16;           // float4 lanes per row
static constexpr int RPT    = 8;            // rows per thread
static constexpr int BLOCK  = 256;
static constexpr int ROWS_PER_BLOCK = (BLOCK / LANES) * RPT;  // 128

__global__ __launch_bounds__(BLOCK)
void gather_main(const int* __restrict__ indices,
                 const float4* __restrict__ table4,
                 float4* __restrict__ out4)
{
    const unsigned local_row = threadIdx.x >> 4;   // 0..15
    const unsigned lane      = threadIdx.x & 15u;  // 0..15
    const unsigned row_base  = blockIdx.x * (unsigned)ROWS_PER_BLOCK + local_row;

    unsigned idx[RPT];
    float4   vals[RPT];

    // Phase 1: batched independent index loads (L1-broadcast across lanes)
#pragma unroll
    for (int k = 0; k < RPT; k++)
        idx[k] = (unsigned)__ldg(indices + row_base + k * LANES);

    // Phase 2: batched independent table gathers (u32 float4 offsets)
#pragma unroll
    for (int k = 0; k < RPT; k++)
        vals[k] = __ldg(table4 + idx[k] * (unsigned)(D / 4) + lane);

    // Phase 3: streaming stores (evict-first; output is write-once)
#pragma unroll
    for (int k = 0; k < RPT; k++)
        __stcs(out4 + (row_base + k * LANES) * (unsigned)(D / 4) + lane, vals[k]);
}

__global__ __launch_bounds__(BLOCK)
void gather_tail(const int* __restrict__ indices,
                 const float4* __restrict__ table4,
                 float4* __restrict__ out4,
                 unsigned row_start, unsigned n_rows)
{
    const unsigned row  = row_start + blockIdx.x * (BLOCK / LANES) + (threadIdx.x >> 4);
    const unsigned lane = threadIdx.x & 15u;
    if (row >= n_rows) return;
    const unsigned idx = (unsigned)__ldg(indices + row);
    __stcs(out4 + row * (unsigned)(D / 4) + lane,
           __ldg(table4 + idx * (unsigned)(D / 4) + lane));
}

extern "C" void kernel_launch(void* const* d_in, const int* in_sizes, int n_in,
                              void* d_out, int out_size)
{
    const int*    indices = (const int*)d_in[0];
    const float4* table4  = (const float4*)d_in[1];
    float4*       out4    = (float4*)d_out;

    const unsigned n_rows    = (unsigned)in_sizes[0];          // 819200
    const unsigned full_blks = n_rows / ROWS_PER_BLOCK;        // 6400 (exact)
    const unsigned done      = full_blks * ROWS_PER_BLOCK;

    if (full_blks)
        gather_main<<<full_blks, BLOCK>>>(indices, table4, out4);

    if (done < n_rows) {
        const unsigned rem   = n_rows - done;
        const unsigned blks  = (rem * LANES + BLOCK - 1) / BLOCK;
        gather_tail<<<blks, BLOCK>>>(indices, table4, out4, done, n_rows);
    }
}